// round 16
// baseline (speedup 1.0000x reference)
#include <cuda_runtime.h>
#include <cuda_fp16.h>

#define NTHREADS 256
#define BLOCKS_PER_SM 2
#define NBLOCKS  (148 * BLOCKS_PER_SM)   // persistent grid

// fp16 row-pair dup: entry(y,x) = 32B = [tex(y,x) ranks0-7, tex(y+1,x) ranks0-7]
// (y+1 clamped). One bilinear sample = 64B contiguous (entries xb, xb+1).
// uint4 slots within the 64B: [top(x0), bot(x0), top(x1), bot(x1)]
#define DUP_U4 (512 * 512 * 2)           // uint4 per plane = 8MB/plane, 24MB total
__device__ uint4 g_dup[3][DUP_U4];

__global__ void __launch_bounds__(256)
repack_kernel(const float4* __restrict__ p0,
              const float4* __restrict__ p1,
              const float4* __restrict__ p2)
{
    const int idx = blockIdx.x * 256 + threadIdx.x;   // one thread per output uint4
    if (idx >= 3 * DUP_U4) return;
    const int q   = idx >> 19;             // plane
    const int rem = idx & (DUP_U4 - 1);
    const int ent = rem >> 1;              // entry = y*512 + x
    const int bot = rem & 1;
    const int y   = ent >> 9;
    const int x   = ent & 511;
    const int yy  = bot ? min(y + 1, 511) : y;
    const float4* src = (q == 0) ? p0 : (q == 1) ? p1 : p2;
    const float4 f0 = __ldg(src + ((((yy << 9) + x) << 1) + 0));
    const float4 f1 = __ldg(src + ((((yy << 9) + x) << 1) + 1));
    __half2 h01 = __floats2half2_rn(f0.x, f0.y);
    __half2 h23 = __floats2half2_rn(f0.z, f0.w);
    __half2 h45 = __floats2half2_rn(f1.x, f1.y);
    __half2 h67 = __floats2half2_rn(f1.z, f1.w);
    uint4 o;
    o.x = *reinterpret_cast<unsigned*>(&h01);
    o.y = *reinterpret_cast<unsigned*>(&h23);
    o.z = *reinterpret_cast<unsigned*>(&h45);
    o.w = *reinterpret_cast<unsigned*>(&h67);
    g_dup[q][rem] = o;
}

// ---- packed f32x2 helpers (sm_100+) ----
__device__ __forceinline__ unsigned long long pack2(float lo, float hi) {
    unsigned long long r;
    asm("mov.b64 %0, {%1,%2};" : "=l"(r) : "f"(lo), "f"(hi));
    return r;
}
__device__ __forceinline__ void unpack2(unsigned long long v, float& lo, float& hi) {
    asm("mov.b64 {%0,%1}, %2;" : "=f"(lo), "=f"(hi) : "l"(v));
}
__device__ __forceinline__ void fma2(unsigned long long& d,
                                     unsigned long long a, unsigned long long b) {
    asm("fma.rn.f32x2 %0, %1, %2, %0;" : "+l"(d) : "l"(a), "l"(b));
}

struct Inflight {
    __half2 woa, wra, wob, wrb, woc, wrc;   // own-row / recv-row weights, broadcast half2
    uint4 va, vb, vc;
};

// per-coordinate processing (once per coord; [-1,1] pre-clip subsumed by [0,511]
// clamp under the monotone map c*256 + 255.5)
__device__ __forceinline__ void coord_proc(float c, float& frac, float& omf, int& ib)
{
    float X = fmaf(c, 256.0f, 255.5f);
    X = fminf(fmaxf(X, 0.0f), 511.0f);
    float F = fminf(floorf(X), 510.0f);   // frac==1 exactly at border 511
    frac = X - F;
    omf  = 1.0f - frac;
    ib   = (int)F;
}

__device__ __forceinline__ void issue_gathers(
    Inflight& g, float cx, float cy, float cz, int s, int h, int p,
    const uint4* __restrict__ dxy, const uint4* __restrict__ dxz,
    const uint4* __restrict__ dyz)
{
    float fx, ox; int ix;  coord_proc(cx, fx, ox, ix);
    float fy, oy; int iy;  coord_proc(cy, fy, oy, iy);
    float fz, oz; int iz;  coord_proc(cz, fz, oz, iz);

    const float apx = p ? fx : ox;       // x as column (planes xy, xz)
    const float apy = p ? fy : oy;       // y as column (plane yz)
    const float ryo = h ? fy : oy;       // y as row: own corner row = h
    const float ryr = h ? oy : fy;
    const float rzo = h ? fz : oz;       // z as row
    const float rzr = h ? oz : fz;

    g.woa = __float2half2_rn(apx * ryo);
    g.wra = __float2half2_rn(apx * ryr);
    g.wob = __float2half2_rn(apx * rzo);
    g.wrb = __float2half2_rn(apx * rzr);
    g.woc = __float2half2_rn(apy * rzo);
    g.wrc = __float2half2_rn(apy * rzr);

    const int ba = (((iy << 9) + ix) << 1) + s;
    const int bb = (((iz << 9) + ix) << 1) + s;
    const int bc = (((iz << 9) + iy) << 1) + s;

    g.va = __ldg(dxy + ba);
    g.vb = __ldg(dxz + bb);
    g.vc = __ldg(dyz + bc);
}

// per-plane: exchange rank-halves (2 shfl), packed fp16 row-lerp -> 2 half2 features
__device__ __forceinline__ void plane_pf_h2(
    const uint4& v, __half2 wo, __half2 wr, int h, __half2& pf0, __half2& pf1)
{
    unsigned own0 = h ? v.z : v.x;       // keep our h half (ranks h*4..h*4+3)
    unsigned own1 = h ? v.w : v.y;
    unsigned snd0 = h ? v.x : v.z;       // send partner our (1-h) half
    unsigned snd1 = h ? v.y : v.w;
    unsigned r0 = __shfl_xor_sync(0xffffffffu, snd0, 1);
    unsigned r1 = __shfl_xor_sync(0xffffffffu, snd1, 1);
    __half2 o0 = *reinterpret_cast<__half2*>(&own0);
    __half2 o1 = *reinterpret_cast<__half2*>(&own1);
    __half2 q0 = *reinterpret_cast<__half2*>(&r0);
    __half2 q1 = *reinterpret_cast<__half2*>(&r1);
    pf0 = __hfma2(wo, o0, __hmul2(wr, q0));
    pf1 = __hfma2(wo, o1, __hmul2(wr, q1));
}

__device__ __forceinline__ void consume_store(
    const Inflight& g, const unsigned long long* __restrict__ W2,
    const float* __restrict__ bias, int i, int n, int h, int grp,
    float* __restrict__ out)
{
    __half2 pf[6];
    plane_pf_h2(g.va, g.woa, g.wra, h, pf[0], pf[1]);
    plane_pf_h2(g.vb, g.wob, g.wrb, h, pf[2], pf[3]);
    plane_pf_h2(g.vc, g.woc, g.wrc, h, pf[4], pf[5]);

    // packed column reduce (xor bit1) + convert to packed fp32 feature pairs
    unsigned long long gg2[6];
    #pragma unroll
    for (int q2 = 0; q2 < 6; q2++) {
        unsigned u = *reinterpret_cast<unsigned*>(&pf[q2]);
        unsigned w = __shfl_xor_sync(0xffffffffu, u, 2);
        __half2 sum = __hadd2(pf[q2], *reinterpret_cast<__half2*>(&w));
        float2 f = __half22float2(sum);
        gg2[q2] = pack2(f.x, f.y);
    }

    // packed fp32 matvec: 2 interleaved partial sums per output, bias folded in
    unsigned long long a0 = pack2(bias[0], 0.f);
    unsigned long long a1 = pack2(bias[1], 0.f);
    unsigned long long a2 = pack2(bias[2], 0.f);
    unsigned long long a3 = pack2(bias[3], 0.f);
    #pragma unroll
    for (int q2 = 0; q2 < 6; q2++) {
        fma2(a0, W2[q2],      gg2[q2]);
        fma2(a1, W2[6 + q2],  gg2[q2]);
        fma2(a2, W2[12 + q2], gg2[q2]);
        fma2(a3, W2[18 + q2], gg2[q2]);
    }
    float l, hh;
    unpack2(a0, l, hh);  float o0 = l + hh;
    unpack2(a1, l, hh);  float o1 = l + hh;
    unpack2(a2, l, hh);  float o2 = l + hh;
    unpack2(a3, l, hh);  float o3 = l + hh;

    o0 += __shfl_xor_sync(0xffffffffu, o0, 1);
    o1 += __shfl_xor_sync(0xffffffffu, o1, 1);
    o2 += __shfl_xor_sync(0xffffffffu, o2, 1);
    o3 += __shfl_xor_sync(0xffffffffu, o3, 1);

    if (i < n && h == 0) {
        float4 v;
        v.x = fminf(fmaxf(o0, -10.0f), 10.0f);
        v.y = fminf(fmaxf(o1, -10.0f), 10.0f);
        v.z = fminf(fmaxf(o2, -10.0f), 10.0f);
        v.w = fminf(fmaxf(o3, -10.0f), 10.0f);
        reinterpret_cast<float4*>(out)[(i << 1) + grp] = v;
    }
}

__global__ void __launch_bounds__(NTHREADS, BLOCKS_PER_SM)
geo_encoder_kernel(
    const float*  __restrict__ coords,   // [N,3]
    const float*  __restrict__ Wp,       // [8,24]
    const float*  __restrict__ bp,       // [8]
    float*        __restrict__ out,      // [N,8]
    int n)
{
    const uint4* __restrict__ dxy = g_dup[0];
    const uint4* __restrict__ dxz = g_dup[1];
    const uint4* __restrict__ dyz = g_dup[2];

    const int t   = threadIdx.x;
    const int s   = t & 3;
    const int h   = s & 1;       // rank half kept + own corner row
    const int p   = s >> 1;      // column; also output group
    const int grp = p;

    // W2[j*6 + q2] = packed pair (W[4*grp+j][feat(2q2)], W[4*grp+j][feat(2q2+1)])
    // feature order = plane-major, this lane's rank-half: q*8 + h*4 + rr
    unsigned long long W2[24];
    float bias[4];
    const int row0 = 4 * grp;
    #pragma unroll
    for (int j = 0; j < 4; j++) {
        bias[j] = __ldg(bp + row0 + j) * 0.5f;   // bias split across the 2 half-lanes? NO
        #pragma unroll
        for (int q = 0; q < 3; q++)
            #pragma unroll
            for (int rp = 0; rp < 2; rp++) {
                float wlo = __ldg(Wp + (row0 + j) * 24 + q * 8 + h * 4 + 2 * rp);
                float whi = __ldg(Wp + (row0 + j) * 24 + q * 8 + h * 4 + 2 * rp + 1);
                W2[j * 6 + q * 2 + rp] = pack2(wlo, whi);
            }
    }
    // bias correction: the xor1 output combine sums BOTH half-lanes' accumulators,
    // so each lane must contribute bias/2 (h==0 and h==1 both fold bias in).
    // (bias[j] already scaled by 0.5 above.)

    const int quad   = (blockIdx.x * NTHREADS + t) >> 2;
    const int nquads = (NBLOCKS * NTHREADS) >> 2;
    const int niter  = (n + nquads - 1) / nquads;

    auto ldc = [&](int j, float& x, float& y, float& z) {
        int i  = quad + j * nquads;
        int ie = (i < n) ? i : 0;
        x = __ldg(coords + 3 * ie + 0);
        y = __ldg(coords + 3 * ie + 1);
        z = __ldg(coords + 3 * ie + 2);
    };

    float x0, y0, z0;  ldc(0, x0, y0, z0);
    float xA, yA, zA;  ldc(1, xA, yA, zA);
    float xB, yB, zB;  ldc(2, xB, yB, zB);

    Inflight GA, GB;
    issue_gathers(GA, x0, y0, z0, s, h, p, dxy, dxz, dyz);

    for (int k = 0; k < niter; k += 2) {
        issue_gathers(GB, xA, yA, zA, s, h, p, dxy, dxz, dyz);
        ldc(k + 3, xA, yA, zA);
        consume_store(GA, W2, bias, quad + k * nquads, n, h, grp, out);

        issue_gathers(GA, xB, yB, zB, s, h, p, dxy, dxz, dyz);
        ldc(k + 4, xB, yB, zB);
        consume_store(GB, W2, bias, quad + (k + 1) * nquads, n, h, grp, out);
    }
}

extern "C" void kernel_launch(void* const* d_in, const int* in_sizes, int n_in,
                              void* d_out, int out_size)
{
    const float*  coords = (const float*)d_in[0];
    const float4* pxy    = (const float4*)d_in[1];
    const float4* pxz    = (const float4*)d_in[2];
    const float4* pyz    = (const float4*)d_in[3];
    const float*  Wp     = (const float*)d_in[4];
    const float*  bp     = (const float*)d_in[5];
    float*        out    = (float*)d_out;

    const int n = in_sizes[0] / 3;

    repack_kernel<<<(3 * DUP_U4) / 256, 256>>>(pxy, pxz, pyz);
    geo_encoder_kernel<<<NBLOCKS, NTHREADS>>>(coords, Wp, bp, out, n);
}